// round 7
// baseline (speedup 1.0000x reference)
#include <cuda_runtime.h>

// MxAssemble: out[b,c,y,x] = sum_{dy,dx in [0,13)} aff[b, dy*13+dx, y, x] * in2zp[b, c, y+dy-6, x+dx-6]
// B=4, D=169, C=64, H=W=192, fp32.
// f32x2-packed inner product; rolling base pointers so all LDG/LDS use
// immediate offsets; aff row software-prefetched one dy ahead.

#define BB   4
#define CC   64
#define HH   192
#define WW   192
#define WIN  13
#define DD   169
#define HWSZ (HH*WW)

#define TW    64     // x pixels per block
#define TH    8      // y rows per block
#define CBLK  16     // channels per block
#define CPT   8      // channels per thread
#define XR    4      // x pixels per thread
#define SROWS (TH+12)   // 20
#define SPITCH 80       // floats per smem row (320B, 16B aligned)

typedef unsigned long long u64t;

__device__ __forceinline__ u64t ffma2(u64t a, u64t b, u64t c) {
    u64t d;
    asm("fma.rn.f32x2 %0, %1, %2, %3;" : "=l"(d) : "l"(a), "l"(b), "l"(c));
    return d;
}
__device__ __forceinline__ u64t packf2(float lo, float hi) {
    u64t d;
    asm("mov.b64 %0, {%1, %2};" : "=l"(d) : "f"(lo), "f"(hi));
    return d;
}
__device__ __forceinline__ void unpackf2(u64t v, float& lo, float& hi) {
    asm("mov.b64 {%0, %1}, %2;" : "=f"(lo), "=f"(hi) : "l"(v));
}
__device__ __forceinline__ void pf_l1(const float* p) {
    asm volatile("prefetch.global.L1 [%0];" :: "l"(p));
}

__global__ __launch_bounds__(256, 2)
void mxassemble_kernel(const float* __restrict__ aff,
                       const float* __restrict__ in2,
                       float* __restrict__ out)
{
    __shared__ __align__(16) float s[CBLK][SROWS][SPITCH];

    const int tx = threadIdx.x;      // 0..15  -> x group
    const int ty = threadIdx.y;      // 0..15
    const int yy = ty & 7;           // row within tile
    const int ch = ty >> 3;          // channel half (0/1)

    const int bx = blockIdx.x;       // 12 = 4 cgroups * 3 xtiles, cgroup fastest
    const int cg = bx & 3;
    const int xt = bx >> 2;
    const int yt = blockIdx.y;       // 0..23
    const int b  = blockIdx.z;       // 0..3

    const int x0 = xt * TW;
    const int y0 = yt * TH;
    const int c0 = cg * CBLK;

    // ---- cooperative smem fill -------------------------------------------
    // 6400 quads = 16 planes x 20 rows x 20 aligned global quads (gxq = x0-8+4q).
    // Incremental (q, rr, cc) decomposition: no div/mod in the loop.
    {
        const float* in2b = in2 + (size_t)b * CC * HWSZ;
        const int tid = ty * 16 + tx;
        int q  = tid % 20;
        int t2 = tid / 20;
        int rr = t2 % 20;
        int cc = t2 / 20;
        #pragma unroll 1
        for (int it = 0; it < 25; it++) {
            const int gy  = y0 - 6 + rr;
            const int gxq = x0 - 8 + 4 * q;

            float4 v = make_float4(0.f, 0.f, 0.f, 0.f);
            if ((unsigned)gy < (unsigned)HH) {
                const float* src = in2b + (size_t)(c0 + cc) * HWSZ + gy * WW + gxq;
                if (gxq >= 0 && gxq <= WW - 4) {
                    v = *(const float4*)src;
                } else {
                    if ((unsigned)(gxq + 0) < (unsigned)WW) v.x = src[0];
                    if ((unsigned)(gxq + 1) < (unsigned)WW) v.y = src[1];
                    if ((unsigned)(gxq + 2) < (unsigned)WW) v.z = src[2];
                    if ((unsigned)(gxq + 3) < (unsigned)WW) v.w = src[3];
                }
            }
            const int c0q = 4 * q - 2;               // smem col of v.x
            float* dst = &s[cc][rr][0];
            if (c0q >= 0) *(float2*)(dst + c0q) = make_float2(v.x, v.y);
            *(float2*)(dst + c0q + 2) = make_float2(v.z, v.w);

            // advance by 256 quads: 256 = 12*20 + 16
            q += 16; rr += 12;
            if (q >= 20)  { q -= 20; rr += 1; }
            if (rr >= 20) { rr -= 20; cc += 1; }
        }
    }

    // ---- preload aff row for dy=0 (overlaps fill + barrier latency) -------
    const int xs = tx * XR;
    const float* affRow = aff + (size_t)b * DD * HWSZ + (y0 + yy) * WW + x0 + xs;

    ulonglong2 ap[WIN];
    #pragma unroll
    for (int j = 0; j < WIN; j++)
        ap[j] = *(const ulonglong2*)(affRow + j * HWSZ);

    __syncthreads();

    // ---- main accumulation ------------------------------------------------
    u64t accA[CPT], accB[CPT];       // accA: outputs (xs, xs+1), accB: (xs+2, xs+3)
    #pragma unroll
    for (int c = 0; c < CPT; c++) { accA[c] = 0ull; accB[c] = 0ull; }

    const float* sdy = &s[ch * CPT][0][0] + yy * SPITCH + xs;   // rolling smem base

    #pragma unroll 1
    for (int dy = 0; dy < WIN; dy++) {
        // prefetch next dy's aff lines into L1 (no register cost)
        if (dy < WIN - 1) {
            #pragma unroll
            for (int j = 0; j < WIN; j++)
                pf_l1(affRow + (WIN + j) * HWSZ);
        }

        #pragma unroll
        for (int c = 0; c < CPT; c++) {
            const float* srow = sdy + c * (SROWS * SPITCH);
            // 4 aligned LDS.128: r[0..15]
            union { ulonglong2 u; float4 f; } Q[4];
            #pragma unroll
            for (int q = 0; q < 4; q++)
                Q[q].u = *(const ulonglong2*)(srow + 4 * q);

            u64t p[15];                       // p[k] = (r[k], r[k+1])
            #pragma unroll
            for (int q = 0; q < 4; q++) {
                p[4 * q] = Q[q].u.x;          // aligned even pairs -> free
                if (4 * q + 2 <= 14) p[4 * q + 2] = Q[q].u.y;
            }
            #pragma unroll
            for (int t = 0; t < 7; t++) {     // odd pairs: (r[2t+1], r[2t+2])
                const int k = 2 * t + 1;
                const float lo = (k & 2) ? Q[k >> 2].f.w : Q[k >> 2].f.y;
                const int k2 = k + 1;
                const float hi = (k2 & 2) ? Q[k2 >> 2].f.z : Q[k2 >> 2].f.x;
                p[k] = packf2(lo, hi);
            }

            #pragma unroll
            for (int j = 0; j < WIN; j++) {
                accA[c] = ffma2(ap[j].x, p[j],     accA[c]);
                accB[c] = ffma2(ap[j].y, p[j + 2], accB[c]);
            }
        }

        // advance bases; reload ap for next dy (hits L1 via the prefetch above)
        affRow += WIN * HWSZ;
        sdy    += SPITCH;
        if (dy < WIN - 1) {
            #pragma unroll
            for (int j = 0; j < WIN; j++)
                ap[j] = *(const ulonglong2*)(affRow + j * HWSZ);
        }
    }

    // ---- write out --------------------------------------------------------
    float* outp = out + (size_t)b * CC * HWSZ + (y0 + yy) * WW + x0 + xs
                + (size_t)(c0 + ch * CPT) * HWSZ;
    #pragma unroll
    for (int c = 0; c < CPT; c++) {
        float4 v;
        unpackf2(accA[c], v.x, v.y);
        unpackf2(accB[c], v.z, v.w);
        *(float4*)(outp + (size_t)c * HWSZ) = v;
    }
}

extern "C" void kernel_launch(void* const* d_in, const int* in_sizes, int n_in,
                              void* d_out, int out_size)
{
    const float* aff = (const float*)d_in[0];   // [4,169,192,192]
    const float* in2 = (const float*)d_in[1];   // [4,64,192,192]
    float* out = (float*)d_out;                 // [4,64,192,192]

    dim3 grid(12, 24, 4);   // (cgroup*xtile, ytile, batch) — cgroup fastest for aff L2 reuse
    dim3 block(16, 16);
    mxassemble_kernel<<<grid, block>>>(aff, in2, out);
}